// round 12
// baseline (speedup 1.0000x reference)
#include <cuda_runtime.h>

// ---------------------------------------------------------------------------
// DummyGCN4: 4-layer GCN, output = h3[node 1] only.
// R12: ONE critical-path full pass. k_part scatters edges (s,d) into coarse
// buckets keyed by d>>3 (6272 buckets, ~128 edges each, contiguous int2).
// Backward expansions become coalesced bucket-segment filters (no pointer
// chasing, no repeated full scans). agg0all (layer-0 aggregation for ALL
// nodes, no deps) runs on a forked stream concurrently with k_part.
// Tail self-cleans bucket counters / bitmaps / counters for graph replay.
// ---------------------------------------------------------------------------

#define MAXN 50048
#define BMW  1568
#define OUT_NODE 1
#define NB   6272         // buckets: node >> 3  (50176/8)
#define BCAP 384          // mean ~128 edges/bucket; +22 sigma; guarded
#define E1CAP  8192
#define E2CAP  32768
#define EBCAP  262144

__device__ int   g_bc[NB];                         // bucket counts (0 at start)
__device__ int2  g_bk[(size_t)NB * BCAP];          // (src, dst) per slot
__device__ unsigned g_B1[BMW], g_B2[BMW];
__device__ int   g_list1[MAXN], g_list2[MAXN];
__device__ int   g_cnt1, g_cnt2;
__device__ int   g_e1s[E1CAP];                 __device__ int g_e1n;
__device__ int   g_e2s[E2CAP],  g_e2d[E2CAP];  __device__ int g_e2n;
__device__ int   g_ebs[EBCAP],  g_ebd[EBCAP];  __device__ int g_ebn;
__device__ float g_agg0[MAXN];
__device__ float g_agg1[(size_t)MAXN * 64];
__device__ float g_x2[(size_t)MAXN * 64];
__device__ float g_agg2[(size_t)MAXN * 64];
__device__ float g_x3[MAXN];

__device__ __forceinline__ float lrelu(float x) { return x >= 0.f ? x : 0.01f * x; }
__device__ __forceinline__ void zero64(float* a) {
    float4 z = make_float4(0.f, 0.f, 0.f, 0.f);
    float4* a4 = (float4*)a;
    #pragma unroll
    for (int j = 0; j < 16; j++) a4[j] = z;
}

// ---------------- k_part: the ONLY critical-path full pass ----------------
__global__ void k_part(const int* __restrict__ src, const int* __restrict__ dst, int E) {
    int t = blockIdx.x * blockDim.x + threadIdx.x;
    int base = t * 4;
    if (base + 3 < E) {
        int4 d4 = __ldg((const int4*)(dst + base));
        int4 s4 = __ldg((const int4*)(src + base));
        int b, p;
        b = d4.x >> 3; p = atomicAdd(&g_bc[b], 1); if (p < BCAP) g_bk[(size_t)b * BCAP + p] = make_int2(s4.x, d4.x);
        b = d4.y >> 3; p = atomicAdd(&g_bc[b], 1); if (p < BCAP) g_bk[(size_t)b * BCAP + p] = make_int2(s4.y, d4.y);
        b = d4.z >> 3; p = atomicAdd(&g_bc[b], 1); if (p < BCAP) g_bk[(size_t)b * BCAP + p] = make_int2(s4.z, d4.z);
        b = d4.w >> 3; p = atomicAdd(&g_bc[b], 1); if (p < BCAP) g_bk[(size_t)b * BCAP + p] = make_int2(s4.w, d4.w);
    } else {
        for (int e = base; e < E; e++) {
            int d = __ldg(&dst[e]), s = __ldg(&src[e]);
            int b = d >> 3;
            int p = atomicAdd(&g_bc[b], 1);
            if (p < BCAP) g_bk[(size_t)b * BCAP + p] = make_int2(s, d);
        }
    }
}

// ---------------- branch B: zero agg0 then aggregate ALL edges --------------
__global__ void k_zagg0() {
    int t = blockIdx.x * blockDim.x + threadIdx.x;
    if (t < MAXN) g_agg0[t] = 0.f;
}
__global__ void k_agg0all(const int* __restrict__ src, const int* __restrict__ dst,
                          const float* __restrict__ in_feat, int E) {
    int t = blockIdx.x * blockDim.x + threadIdx.x;
    int base = t * 4;
    if (base + 3 < E) {
        int4 d4 = __ldg((const int4*)(dst + base));
        int4 s4 = __ldg((const int4*)(src + base));
        atomicAdd(&g_agg0[d4.x], __ldg(&in_feat[s4.x]));
        atomicAdd(&g_agg0[d4.y], __ldg(&in_feat[s4.y]));
        atomicAdd(&g_agg0[d4.z], __ldg(&in_feat[s4.z]));
        atomicAdd(&g_agg0[d4.w], __ldg(&in_feat[s4.w]));
    } else {
        for (int e = base; e < E; e++)
            atomicAdd(&g_agg0[dst[e]], __ldg(&in_feat[src[e]]));
    }
}

// ---------------- t2: bucket of node 1 -> e1 srcs, B2/list2 ----------------
__global__ void k_t2() {
    int n = min(g_bc[OUT_NODE >> 3], BCAP);
    const int2* b = &g_bk[(size_t)(OUT_NODE >> 3) * BCAP];
    for (int i = threadIdx.x; i < n; i += blockDim.x) {
        int2 e = b[i];
        if (e.y != OUT_NODE) continue;
        int s = e.x;
        int p = atomicAdd(&g_e1n, 1);
        if (p < E1CAP) g_e1s[p] = s;
        unsigned m = 1u << (s & 31);
        unsigned old = atomicOr(&g_B2[s >> 5], m);
        if (!(old & m)) {
            int q = atomicAdd(&g_cnt2, 1);
            g_list2[q] = s;
            zero64(&g_agg2[(size_t)s * 64]);
        }
    }
}

// ---------------- t21: warp per B2 node, scan its bucket -> e2, B1/list1 ----
__global__ void k_t21() {
    int n = g_cnt2;
    int lane = threadIdx.x & 31;
    int warp = (blockIdx.x * blockDim.x + threadIdx.x) >> 5;
    int nw = (gridDim.x * blockDim.x) >> 5;
    for (int i = warp; i < n; i += nw) {
        int v = g_list2[i];
        int bkt = v >> 3;
        int dv = min(g_bc[bkt], BCAP);
        const int2* b = &g_bk[(size_t)bkt * BCAP];
        for (int j = lane; j < dv; j += 32) {
            int2 e = b[j];
            if (e.y != v) continue;
            int s = e.x;
            int p = atomicAdd(&g_e2n, 1);
            if (p < E2CAP) { g_e2s[p] = s; g_e2d[p] = v; }
            unsigned m = 1u << (s & 31);
            unsigned old = atomicOr(&g_B1[s >> 5], m);
            if (!(old & m)) {
                int q = atomicAdd(&g_cnt1, 1);
                g_list1[q] = s;
                zero64(&g_agg1[(size_t)s * 64]);
            }
        }
    }
}

// ---------------- t10: warp per B1 node, scan its bucket -> eb --------------
__global__ void k_t10() {
    int n = g_cnt1;
    int lane = threadIdx.x & 31;
    int warp = (blockIdx.x * blockDim.x + threadIdx.x) >> 5;
    int nw = (gridDim.x * blockDim.x) >> 5;
    for (int i = warp; i < n; i += nw) {
        int v = g_list1[i];
        int bkt = v >> 3;
        int dv = min(g_bc[bkt], BCAP);
        const int2* b = &g_bk[(size_t)bkt * BCAP];
        for (int j = lane; j < dv; j += 32) {
            int2 e = b[j];
            if (e.y != v) continue;
            int p = atomicAdd(&g_ebn, 1);
            if (p < EBCAP) { g_ebs[p] = e.x; g_ebd[p] = v; }
        }
    }
}

// ---------------- agg1: agg1[d][:] += lrelu(agg0[s]*W0+b0), warp/edge -------
__global__ void k_agg1(const float* __restrict__ W0, const float* __restrict__ b0) {
    int n = min(g_ebn, EBCAP);
    int lane = threadIdx.x & 31;
    int warp = (blockIdx.x * blockDim.x + threadIdx.x) >> 5;
    int nw = (gridDim.x * blockDim.x) >> 5;
    float w0a = __ldg(&W0[lane]), w0b = __ldg(&W0[lane + 32]);
    float b0a = __ldg(&b0[lane]), b0b = __ldg(&b0[lane + 32]);
    for (int i = warp; i < n; i += nw) {
        int s = g_ebs[i], d = g_ebd[i];
        float a0 = g_agg0[s];
        float* a = &g_agg1[(size_t)d * 64];
        atomicAdd(&a[lane],      lrelu(fmaf(a0, w0a, b0a)));
        atomicAdd(&a[lane + 32], lrelu(fmaf(a0, w0b, b0b)));
    }
}

// ---------------- h1x2: per node in list1 (warp/node) ----------------
__global__ void k_h1x2(const float* __restrict__ W1, const float* __restrict__ b1,
                       const float* __restrict__ W2) {
    int n = g_cnt1;
    int lane = threadIdx.x & 31;
    int warp = (blockIdx.x * blockDim.x + threadIdx.x) >> 5;
    int nw = (gridDim.x * blockDim.x) >> 5;
    for (int i = warp; i < n; i += nw) {
        int v = g_list1[i];
        float a0 = g_agg1[(size_t)v * 64 + lane];
        float a1 = g_agg1[(size_t)v * 64 + lane + 32];
        float h0r = __ldg(&b1[lane]);
        float h1r = __ldg(&b1[lane + 32]);
        float h2r = __ldg(&b1[lane + 64]);
        float h3r = __ldg(&b1[lane + 96]);
        #pragma unroll
        for (int k = 0; k < 64; k++) {
            float ak = __shfl_sync(0xffffffffu, (k < 32) ? a0 : a1, k & 31);
            const float* wr = &W1[k * 128];
            h0r = fmaf(ak, __ldg(&wr[lane]),      h0r);
            h1r = fmaf(ak, __ldg(&wr[lane + 32]), h1r);
            h2r = fmaf(ak, __ldg(&wr[lane + 64]), h2r);
            h3r = fmaf(ak, __ldg(&wr[lane + 96]), h3r);
        }
        float h[4] = { lrelu(h0r), lrelu(h1r), lrelu(h2r), lrelu(h3r) };
        float x0 = 0.f, x1 = 0.f;
        #pragma unroll
        for (int k = 0; k < 128; k++) {
            float hk = __shfl_sync(0xffffffffu, h[k >> 5], k & 31);
            const float* wr = &W2[k * 64];
            x0 = fmaf(hk, __ldg(&wr[lane]),      x0);
            x1 = fmaf(hk, __ldg(&wr[lane + 32]), x1);
        }
        g_x2[(size_t)v * 64 + lane]      = x0;
        g_x2[(size_t)v * 64 + lane + 32] = x1;
    }
}

// ---------------- tail: agg2 + h2x3 + final + out + CLEANUP (1 block) -------
__global__ void __launch_bounds__(1024, 1)
k_tail(const float* __restrict__ b2, const float* __restrict__ W3,
       const float* __restrict__ b3, float* __restrict__ out) {
    int lane = threadIdx.x & 31;
    int bw = threadIdx.x >> 5;

    int n2 = min(g_e2n, E2CAP);
    for (int i = bw; i < n2; i += 32) {
        int s = g_e2s[i], d = g_e2d[i];
        float* a = &g_agg2[(size_t)d * 64];
        atomicAdd(&a[lane],      __ldcg(&g_x2[(size_t)s * 64 + lane]));
        atomicAdd(&a[lane + 32], __ldcg(&g_x2[(size_t)s * 64 + lane + 32]));
    }
    __syncthreads();

    int n3 = g_cnt2;
    for (int i = bw; i < n3; i += 32) {
        int v = g_list2[i];
        float ya = lrelu(__ldcg(&g_agg2[(size_t)v * 64 + lane])      + __ldg(&b2[lane]));
        float yb = lrelu(__ldcg(&g_agg2[(size_t)v * 64 + lane + 32]) + __ldg(&b2[lane + 32]));
        float p = fmaf(ya, __ldg(&W3[lane]), yb * __ldg(&W3[lane + 32]));
        #pragma unroll
        for (int o = 16; o; o >>= 1) p += __shfl_down_sync(0xffffffffu, p, o);
        if (lane == 0) g_x3[v] = p;
    }
    __syncthreads();

    __shared__ float red[32];
    int n1 = min(g_e1n, E1CAP);
    float s = 0.f;
    for (int i = threadIdx.x; i < n1; i += 1024) s += __ldcg(&g_x3[g_e1s[i]]);
    #pragma unroll
    for (int o = 16; o; o >>= 1) s += __shfl_down_sync(0xffffffffu, s, o);
    if (lane == 0) red[bw] = s;
    __syncthreads();
    if (threadIdx.x < 32) {
        float t = red[lane];
        #pragma unroll
        for (int o = 16; o; o >>= 1) t += __shfl_down_sync(0xffffffffu, t, o);
        if (lane == 0) out[0] = lrelu(t + __ldg(&b3[0]));
    }
    __syncthreads();

    // ---- cleanup for next graph replay ----
    for (int i = threadIdx.x; i < NB; i += 1024) g_bc[i] = 0;
    int c2 = g_cnt2, c1 = g_cnt1;
    for (int i = threadIdx.x; i < c2; i += 1024) { int v = g_list2[i]; g_B2[v >> 5] = 0u; }
    for (int i = threadIdx.x; i < c1; i += 1024) { int v = g_list1[i]; g_B1[v >> 5] = 0u; }
    __syncthreads();
    if (threadIdx.x == 0) {
        g_cnt1 = 0; g_cnt2 = 0; g_e1n = 0; g_e2n = 0; g_ebn = 0;
        __threadfence();
    }
}

// ---------------------------------------------------------------------------
extern "C" void kernel_launch(void* const* d_in, const int* in_sizes, int n_in,
                              void* d_out, int out_size) {
    const float* in_feat = (const float*)d_in[0];
    const int*   src     = (const int*)  d_in[1];
    const int*   dst     = (const int*)  d_in[2];
    const float* W0 = (const float*)d_in[3];
    const float* b0 = (const float*)d_in[4];
    const float* W1 = (const float*)d_in[5];
    const float* b1 = (const float*)d_in[6];
    const float* W2 = (const float*)d_in[7];
    const float* b2 = (const float*)d_in[8];
    const float* W3 = (const float*)d_in[9];
    const float* b3 = (const float*)d_in[10];
    float* out = (float*)d_out;

    int E = in_sizes[1];
    int T = (E + 3) / 4;
    int sb = (T + 255) / 256;            // ~782 blocks per full pass

    static cudaStream_t s2 = nullptr;
    static cudaEvent_t evF = nullptr, evJ = nullptr;
    if (!s2) {
        cudaStreamCreateWithFlags(&s2, cudaStreamNonBlocking);
        cudaEventCreateWithFlags(&evF, cudaEventDisableTiming);
        cudaEventCreateWithFlags(&evJ, cudaEventDisableTiming);
    }

    // fork: branch B (agg0 zero + all-node layer-0 aggregation) || k_part
    cudaEventRecord(evF, 0);
    cudaStreamWaitEvent(s2, evF, 0);
    k_zagg0<<<(MAXN + 255) / 256, 256, 0, s2>>>();
    k_agg0all<<<sb, 256, 0, s2>>>(src, dst, in_feat, E);
    cudaEventRecord(evJ, s2);

    // critical path
    k_part<<<sb, 256>>>(src, dst, E);    // the ONLY critical-path full pass
    k_t2<<<1, 256>>>();
    k_t21<<<1, 512>>>();
    k_t10<<<16, 256>>>();

    cudaStreamWaitEvent(0, evJ, 0);      // join branch B before agg1
    k_agg1<<<128, 256>>>(W0, b0);
    k_h1x2<<<64, 256>>>(W1, b1, W2);
    k_tail<<<1, 1024>>>(b2, W3, b3, out);
}

// round 13
// speedup vs baseline: 1.9298x; 1.9298x over previous
#include <cuda_runtime.h>

// ---------------------------------------------------------------------------
// DummyGCN4: 4-layer GCN, output = h3[node 1] only.
// R13: R2's exact proven backward-slice scan chain (best measured, 39.7us),
// with 4 redundant kernels removed via validated fusions:
//   clear -> scan32 -> scan21 -> scan10 -> agg0 -> agg1(h0 fused)
//         -> h1x2 -> tail(agg2 + h2x3 + final + out)
// Scan kernels are byte-identical in structure to R2 (int4, 4 edges/thread,
// 782x256 grid). 8 graph nodes total.
// ---------------------------------------------------------------------------

#define MAXN 50048
#define BMW  1568
#define OUT_NODE 1
#define E1CAP  16384      // edges with dst == OUT_NODE
#define E2CAP  65536      // edges with dst in B2
#define EBCAP  262144     // edges with dst in B1

__device__ unsigned g_B0[BMW], g_B1[BMW], g_B2[BMW];
__device__ int   g_list1[MAXN], g_list2[MAXN];
__device__ int   g_cnt1, g_cnt2;
__device__ int   g_e1s[E1CAP];                 __device__ int g_e1n;
__device__ int   g_e2s[E2CAP],  g_e2d[E2CAP];  __device__ int g_e2n;
__device__ int   g_ebs[EBCAP],  g_ebd[EBCAP];  __device__ int g_ebn;
__device__ float g_agg0[MAXN];
__device__ float g_agg1[(size_t)MAXN * 64];
__device__ float g_x2[(size_t)MAXN * 64];
__device__ float g_agg2[(size_t)MAXN * 64];
__device__ float g_x3[MAXN];

__device__ __forceinline__ float lrelu(float x) { return x >= 0.f ? x : 0.01f * x; }
__device__ __forceinline__ bool tb(const unsigned* b, int i) {
    return (b[i >> 5] >> (i & 31)) & 1u;
}
__device__ __forceinline__ void zero64(float* a) {
    float4 z = make_float4(0.f, 0.f, 0.f, 0.f);
    float4* a4 = (float4*)a;
    #pragma unroll
    for (int j = 0; j < 16; j++) a4[j] = z;
}

// ---------------- init: clear bitmaps/counters (R2-identical) ----------------
__global__ void k_clear() {
    int t = blockIdx.x * blockDim.x + threadIdx.x;
    if (t < BMW) { g_B0[t] = 0; g_B1[t] = 0; g_B2[t] = 0; }
    if (t == 0) { g_cnt1 = 0; g_cnt2 = 0; g_e1n = 0; g_e2n = 0; g_ebn = 0; }
}

// ---------------- scan 1: dst == OUT_NODE (R2-identical) ----------------
__device__ __forceinline__ void hit32(const int* __restrict__ src, int e) {
    int s = src[e];
    int p = atomicAdd(&g_e1n, 1);
    if (p < E1CAP) g_e1s[p] = s;
    unsigned m = 1u << (s & 31);
    unsigned old = atomicOr(&g_B2[s >> 5], m);
    if (!(old & m)) {
        int q = atomicAdd(&g_cnt2, 1);
        g_list2[q] = s;
        zero64(&g_agg2[(size_t)s * 64]);
    }
}
__global__ void k_scan32(const int* __restrict__ src, const int* __restrict__ dst, int E) {
    int t = blockIdx.x * blockDim.x + threadIdx.x;
    int base = t * 4;
    if (base + 3 < E) {
        int4 d4 = *(const int4*)(dst + base);
        if (d4.x == OUT_NODE) hit32(src, base + 0);
        if (d4.y == OUT_NODE) hit32(src, base + 1);
        if (d4.z == OUT_NODE) hit32(src, base + 2);
        if (d4.w == OUT_NODE) hit32(src, base + 3);
    } else {
        for (int e = base; e < E; e++) if (dst[e] == OUT_NODE) hit32(src, e);
    }
}

// ---------------- scan 2: dst in B2 (R2-identical) ----------------
__device__ __forceinline__ void hit21(const int* __restrict__ src, int e, int d) {
    int s = src[e];
    int p = atomicAdd(&g_e2n, 1);
    if (p < E2CAP) { g_e2s[p] = s; g_e2d[p] = d; }
    unsigned m = 1u << (s & 31);
    unsigned old = atomicOr(&g_B1[s >> 5], m);
    if (!(old & m)) {
        int q = atomicAdd(&g_cnt1, 1);
        g_list1[q] = s;
        zero64(&g_agg1[(size_t)s * 64]);
    }
}
__global__ void k_scan21(const int* __restrict__ src, const int* __restrict__ dst, int E) {
    int t = blockIdx.x * blockDim.x + threadIdx.x;
    int base = t * 4;
    if (base + 3 < E) {
        int4 d4 = *(const int4*)(dst + base);
        if (tb(g_B2, d4.x)) hit21(src, base + 0, d4.x);
        if (tb(g_B2, d4.y)) hit21(src, base + 1, d4.y);
        if (tb(g_B2, d4.z)) hit21(src, base + 2, d4.z);
        if (tb(g_B2, d4.w)) hit21(src, base + 3, d4.w);
    } else {
        for (int e = base; e < E; e++) { int d = dst[e]; if (tb(g_B2, d)) hit21(src, e, d); }
    }
}

// ---------------- scan 3: dst in B1 (R2-identical) ----------------
__device__ __forceinline__ void hit10(const int* __restrict__ src, int e, int d) {
    int s = src[e];
    int p = atomicAdd(&g_ebn, 1);
    if (p < EBCAP) { g_ebs[p] = s; g_ebd[p] = d; }
    unsigned m = 1u << (s & 31);
    unsigned old = atomicOr(&g_B0[s >> 5], m);
    if (!(old & m)) g_agg0[s] = 0.f;
}
__global__ void k_scan10(const int* __restrict__ src, const int* __restrict__ dst, int E) {
    int t = blockIdx.x * blockDim.x + threadIdx.x;
    int base = t * 4;
    if (base + 3 < E) {
        int4 d4 = *(const int4*)(dst + base);
        if (tb(g_B1, d4.x)) hit10(src, base + 0, d4.x);
        if (tb(g_B1, d4.y)) hit10(src, base + 1, d4.y);
        if (tb(g_B1, d4.z)) hit10(src, base + 2, d4.z);
        if (tb(g_B1, d4.w)) hit10(src, base + 3, d4.w);
    } else {
        for (int e = base; e < E; e++) { int d = dst[e]; if (tb(g_B1, d)) hit10(src, e, d); }
    }
}

// ---------------- scan 4: layer-0 aggregation (R2-identical) ----------------
__global__ void k_agg0(const int* __restrict__ src, const int* __restrict__ dst, int E,
                       const float* __restrict__ in_feat) {
    int t = blockIdx.x * blockDim.x + threadIdx.x;
    int base = t * 4;
    if (base + 3 < E) {
        int4 d4 = *(const int4*)(dst + base);
        if (tb(g_B0, d4.x)) atomicAdd(&g_agg0[d4.x], in_feat[src[base + 0]]);
        if (tb(g_B0, d4.y)) atomicAdd(&g_agg0[d4.y], in_feat[src[base + 1]]);
        if (tb(g_B0, d4.z)) atomicAdd(&g_agg0[d4.z], in_feat[src[base + 2]]);
        if (tb(g_B0, d4.w)) atomicAdd(&g_agg0[d4.w], in_feat[src[base + 3]]);
    } else {
        for (int e = base; e < E; e++) {
            int d = dst[e];
            if (tb(g_B0, d)) atomicAdd(&g_agg0[d], in_feat[src[e]]);
        }
    }
}

// ---------------- agg1: agg1[d][:] += lrelu(agg0[s]*W0+b0) (h0 fused) -------
__global__ void k_agg1(const float* __restrict__ W0, const float* __restrict__ b0) {
    int n = min(g_ebn, EBCAP);
    int lane = threadIdx.x & 31;
    int warp = (blockIdx.x * blockDim.x + threadIdx.x) >> 5;
    int nw = (gridDim.x * blockDim.x) >> 5;
    float w0a = __ldg(&W0[lane]), w0b = __ldg(&W0[lane + 32]);
    float b0a = __ldg(&b0[lane]), b0b = __ldg(&b0[lane + 32]);
    for (int i = warp; i < n; i += nw) {
        int s = g_ebs[i], d = g_ebd[i];
        float a0 = g_agg0[s];
        float* a = &g_agg1[(size_t)d * 64];
        atomicAdd(&a[lane],      lrelu(fmaf(a0, w0a, b0a)));
        atomicAdd(&a[lane + 32], lrelu(fmaf(a0, w0b, b0b)));
    }
}

// ---------------- h1x2: per node in list1 (warp/node, x2 fused) -------------
__global__ void k_h1x2(const float* __restrict__ W1, const float* __restrict__ b1,
                       const float* __restrict__ W2) {
    int n = g_cnt1;
    int lane = threadIdx.x & 31;
    int warp = (blockIdx.x * blockDim.x + threadIdx.x) >> 5;
    int nw = (gridDim.x * blockDim.x) >> 5;
    for (int i = warp; i < n; i += nw) {
        int v = g_list1[i];
        float a0 = g_agg1[(size_t)v * 64 + lane];
        float a1 = g_agg1[(size_t)v * 64 + lane + 32];
        float h0r = __ldg(&b1[lane]);
        float h1r = __ldg(&b1[lane + 32]);
        float h2r = __ldg(&b1[lane + 64]);
        float h3r = __ldg(&b1[lane + 96]);
        #pragma unroll
        for (int k = 0; k < 64; k++) {
            float ak = __shfl_sync(0xffffffffu, (k < 32) ? a0 : a1, k & 31);
            const float* wr = &W1[k * 128];
            h0r = fmaf(ak, __ldg(&wr[lane]),      h0r);
            h1r = fmaf(ak, __ldg(&wr[lane + 32]), h1r);
            h2r = fmaf(ak, __ldg(&wr[lane + 64]), h2r);
            h3r = fmaf(ak, __ldg(&wr[lane + 96]), h3r);
        }
        float h[4] = { lrelu(h0r), lrelu(h1r), lrelu(h2r), lrelu(h3r) };
        float x0 = 0.f, x1 = 0.f;
        #pragma unroll
        for (int k = 0; k < 128; k++) {
            float hk = __shfl_sync(0xffffffffu, h[k >> 5], k & 31);
            const float* wr = &W2[k * 64];
            x0 = fmaf(hk, __ldg(&wr[lane]),      x0);
            x1 = fmaf(hk, __ldg(&wr[lane + 32]), x1);
        }
        g_x2[(size_t)v * 64 + lane]      = x0;
        g_x2[(size_t)v * 64 + lane + 32] = x1;
    }
}

// ---------------- tail: agg2 + h2x3 + final reduce + out (1 block) ----------
__global__ void __launch_bounds__(1024, 1)
k_tail(const float* __restrict__ b2, const float* __restrict__ W3,
       const float* __restrict__ b3, float* __restrict__ out) {
    int lane = threadIdx.x & 31;
    int bw = threadIdx.x >> 5;

    int n2 = min(g_e2n, E2CAP);
    for (int i = bw; i < n2; i += 32) {
        int s = g_e2s[i], d = g_e2d[i];
        float* a = &g_agg2[(size_t)d * 64];
        atomicAdd(&a[lane],      __ldcg(&g_x2[(size_t)s * 64 + lane]));
        atomicAdd(&a[lane + 32], __ldcg(&g_x2[(size_t)s * 64 + lane + 32]));
    }
    __syncthreads();

    int n3 = g_cnt2;
    for (int i = bw; i < n3; i += 32) {
        int v = g_list2[i];
        float ya = lrelu(__ldcg(&g_agg2[(size_t)v * 64 + lane])      + __ldg(&b2[lane]));
        float yb = lrelu(__ldcg(&g_agg2[(size_t)v * 64 + lane + 32]) + __ldg(&b2[lane + 32]));
        float p = fmaf(ya, __ldg(&W3[lane]), yb * __ldg(&W3[lane + 32]));
        #pragma unroll
        for (int o = 16; o; o >>= 1) p += __shfl_down_sync(0xffffffffu, p, o);
        if (lane == 0) g_x3[v] = p;
    }
    __syncthreads();

    __shared__ float red[32];
    int n1 = min(g_e1n, E1CAP);
    float s = 0.f;
    for (int i = threadIdx.x; i < n1; i += 1024) s += __ldcg(&g_x3[g_e1s[i]]);
    #pragma unroll
    for (int o = 16; o; o >>= 1) s += __shfl_down_sync(0xffffffffu, s, o);
    if (lane == 0) red[bw] = s;
    __syncthreads();
    if (threadIdx.x < 32) {
        float t = red[lane];
        #pragma unroll
        for (int o = 16; o; o >>= 1) t += __shfl_down_sync(0xffffffffu, t, o);
        if (lane == 0) out[0] = lrelu(t + __ldg(&b3[0]));
    }
}

// ---------------------------------------------------------------------------
extern "C" void kernel_launch(void* const* d_in, const int* in_sizes, int n_in,
                              void* d_out, int out_size) {
    const float* in_feat = (const float*)d_in[0];
    const int*   src     = (const int*)  d_in[1];
    const int*   dst     = (const int*)  d_in[2];
    const float* W0 = (const float*)d_in[3];
    const float* b0 = (const float*)d_in[4];
    const float* W1 = (const float*)d_in[5];
    const float* b1 = (const float*)d_in[6];
    const float* W2 = (const float*)d_in[7];
    const float* b2 = (const float*)d_in[8];
    const float* W3 = (const float*)d_in[9];
    const float* b3 = (const float*)d_in[10];
    float* out = (float*)d_out;

    int E = in_sizes[1];
    int T = (E + 3) / 4;                 // one thread per 4 edges (R2 config)
    int sb = (T + 255) / 256;            // ~782 blocks

    k_clear<<<(BMW + 255) / 256, 256>>>();
    k_scan32<<<sb, 256>>>(src, dst, E);
    k_scan21<<<sb, 256>>>(src, dst, E);
    k_scan10<<<sb, 256>>>(src, dst, E);
    k_agg0<<<sb, 256>>>(src, dst, E, in_feat);
    k_agg1<<<256, 256>>>(W0, b0);
    k_h1x2<<<512, 128>>>(W1, b1, W2);
    k_tail<<<1, 1024>>>(b2, W3, b3, out);
}